// round 2
// baseline (speedup 1.0000x reference)
#include <cuda_runtime.h>
#include <cstddef>

typedef unsigned long long ULL;

#define EPSF 1e-5f
#define NB 8
#define HW 256
#define NODES 340      // 4 views * 5 T * 17 V
#define ST 20          // activation row stride (floats), 16B aligned

// ---- parameter table layout (floats, all bases 16B-aligned) ----
#define P_ASP 0          // 4*17*17 = 1156
#define P_ATM 1160       // 2*5*5 = 50
#define P_AVW 1212       // 4*4 = 16
#define P_WG0 1228       // 7*18*16 = 2016   [k][c][o]
#define P_WG1 3244       // 7*16*16 = 1792
#define P_WG2 5036       // 1792
#define P_BG  6828       // 3*7*16 = 336
#define P_S1  7164       // 336  (bn1g * rsqrt(1+eps))
#define P_B1  7500       // 336
#define P_WT  7836       // 3*7*16*16 = 5376 [l][k][c][o]
#define P_S2  13212      // 336  (bn2g * rsqrt(1+eps))
#define P_CI  13548      // 3*16 (sum_k bt*s2 + b2)
#define P_TOT 13596

#define S_ACT 13600
#define SM_FLOATS (S_ACT + NODES*ST)   // 20400
#define SM_BYTES  (SM_FLOATS * 4)      // 81600 B -> 2 CTAs/SM

__device__ float gP[P_TOT];

// ---- packed-f32x2 helpers (Blackwell) ----
__device__ __forceinline__ ULL f2fma(ULL a, ULL b, ULL c){
  ULL d; asm("fma.rn.f32x2 %0,%1,%2,%3;" : "=l"(d) : "l"(a), "l"(b), "l"(c)); return d;
}
__device__ __forceinline__ ULL pkdup(float a){
  ULL d; asm("mov.b64 %0,{%1,%1};" : "=l"(d) : "f"(a), "f"(a)); return d;
}
__device__ __forceinline__ ULL pk(float a, float b){
  ULL d; asm("mov.b64 %0,{%1,%2};" : "=l"(d) : "f"(a), "f"(b)); return d;
}
__device__ __forceinline__ float2 up2(ULL a){
  float2 v; asm("mov.b64 {%0,%1},%2;" : "=f"(v.x), "=f"(v.y) : "l"(a)); return v;
}
__device__ __forceinline__ ULL lds2(const float* p){ return *reinterpret_cast<const ULL*>(p); }

// ---------------- prep: fold BN, transpose weights, stage A matrices ----------------
__global__ void prep_kernel(const float* __restrict__ A_sp, const float* __restrict__ A_tm,
                            const float* __restrict__ A_vw,
                            const float* __restrict__ Wg0, const float* __restrict__ bg0,
                            const float* __restrict__ Wg,  const float* __restrict__ bg,
                            const float* __restrict__ bn1g, const float* __restrict__ bn1b,
                            const float* __restrict__ Wt,  const float* __restrict__ bt,
                            const float* __restrict__ bn2g, const float* __restrict__ bn2b)
{
  const int t = threadIdx.x;
  const float inv = rsqrtf(1.f + EPSF);
  for (int i = t; i < 1156; i += 256) gP[P_ASP + i] = A_sp[i];
  for (int i = t; i < 50;   i += 256) gP[P_ATM + i] = A_tm[i];
  for (int i = t; i < 16;   i += 256) gP[P_AVW + i] = A_vw[i];
  // Wg0: (7,16,18) [k][o][c] -> [k][c][o]
  for (int i = t; i < 7*16*18; i += 256){
    int k = i / 288, r = i % 288, o = r / 18, c = r % 18;
    gP[P_WG0 + (k*18 + c)*16 + o] = Wg0[i];
  }
  // Wg: (2,7,16,16) -> per-layer [k][c][o]
  for (int i = t; i < 2*7*256; i += 256){
    int l = i / 1792, r = i % 1792, k = r / 256, q = r % 256, o = q / 16, c = q % 16;
    gP[P_WG1 + l*1792 + (k*16 + c)*16 + o] = Wg[i];
  }
  for (int i = t; i < 112; i += 256) gP[P_BG + i] = bg0[i];
  for (int i = t; i < 224; i += 256) gP[P_BG + 112 + i] = bg[i];
  for (int i = t; i < 336; i += 256){
    gP[P_S1 + i] = bn1g[i] * inv;
    gP[P_B1 + i] = bn1b[i];
    gP[P_S2 + i] = bn2g[i] * inv;
  }
  // Wt: (3,7,16,16) [b][o][c] -> [b][c][o]
  for (int i = t; i < 3*7*256; i += 256){
    int b = i / 256, q = i % 256, o = q / 16, c = q % 16;
    gP[P_WT + b*256 + c*16 + o] = Wt[i];
  }
  // CINIT[l][o] = sum_k ( bt*s2 + b2 )
  for (int i = t; i < 48; i += 256){
    int l = i / 16, o = i % 16;
    float s = 0.f;
    for (int k = 0; k < 7; k++){
      int id = (l*7 + k)*16 + o;
      s += bt[id] * (bn2g[id] * inv) + bn2b[id];
    }
    gP[P_CI + i] = s;
  }
}

// ---- phase A: conv1 (Wg) + bg -> y rows in sA ----
template<int CIN>
__device__ __forceinline__ void conv_a(const float* __restrict__ W, const float* __restrict__ Bg,
                                       const float (&xr0)[18], const float (&xr1)[18],
                                       float* sA, int nd0, int nd1, bool has2)
{
  ULL y0[8], y1[8];
  #pragma unroll
  for (int q = 0; q < 4; q++){
    ulonglong2 b = *reinterpret_cast<const ulonglong2*>(Bg + 4*q);
    y0[2*q] = b.x; y0[2*q+1] = b.y;
    y1[2*q] = b.x; y1[2*q+1] = b.y;
  }
  #pragma unroll
  for (int c = 0; c < CIN; c++){
    ULL xa = pkdup(xr0[c]), xb = pkdup(xr1[c]);
    #pragma unroll
    for (int q = 0; q < 4; q++){
      ulonglong2 wp = *reinterpret_cast<const ulonglong2*>(W + c*16 + 4*q);
      y0[2*q]   = f2fma(wp.x, xa, y0[2*q]);
      y0[2*q+1] = f2fma(wp.y, xa, y0[2*q+1]);
      y1[2*q]   = f2fma(wp.x, xb, y1[2*q]);
      y1[2*q+1] = f2fma(wp.y, xb, y1[2*q+1]);
    }
  }
  ulonglong2* d0 = reinterpret_cast<ulonglong2*>(sA + nd0*ST);
  #pragma unroll
  for (int q = 0; q < 4; q++){ ulonglong2 t; t.x = y0[2*q]; t.y = y0[2*q+1]; d0[q] = t; }
  if (has2){
    ulonglong2* d1 = reinterpret_cast<ulonglong2*>(sA + nd1*ST);
    #pragma unroll
    for (int q = 0; q < 4; q++){ ulonglong2 t; t.x = y1[2*q]; t.y = y1[2*q+1]; d1[q] = t; }
  }
}

// ---- BN1/ReLU + conv2 (Wt) + BN2 -> acc ----
__device__ __forceinline__ void post_agg(const float* __restrict__ W2,
                                         const float* __restrict__ S1, const float* __restrict__ B1,
                                         const float* __restrict__ S2,
                                         ULL (&ag0)[8], ULL (&ag1)[8],
                                         ULL (&acc0)[8], ULL (&acc1)[8])
{
  float r0[16], r1[16];
  #pragma unroll
  for (int q = 0; q < 4; q++){
    ulonglong2 s = *reinterpret_cast<const ulonglong2*>(S1 + 4*q);
    ulonglong2 b = *reinterpret_cast<const ulonglong2*>(B1 + 4*q);
    float2 t;
    t = up2(f2fma(ag0[2*q],   s.x, b.x)); r0[4*q]   = fmaxf(t.x,0.f); r0[4*q+1] = fmaxf(t.y,0.f);
    t = up2(f2fma(ag0[2*q+1], s.y, b.y)); r0[4*q+2] = fmaxf(t.x,0.f); r0[4*q+3] = fmaxf(t.y,0.f);
    t = up2(f2fma(ag1[2*q],   s.x, b.x)); r1[4*q]   = fmaxf(t.x,0.f); r1[4*q+1] = fmaxf(t.y,0.f);
    t = up2(f2fma(ag1[2*q+1], s.y, b.y)); r1[4*q+2] = fmaxf(t.x,0.f); r1[4*q+3] = fmaxf(t.y,0.f);
  }
  ULL z0[8], z1[8];
  #pragma unroll
  for (int op = 0; op < 8; op++){ z0[op] = 0ULL; z1[op] = 0ULL; }
  #pragma unroll
  for (int c = 0; c < 16; c++){
    ULL xa = pkdup(r0[c]), xb = pkdup(r1[c]);
    #pragma unroll
    for (int q = 0; q < 4; q++){
      ulonglong2 wp = *reinterpret_cast<const ulonglong2*>(W2 + c*16 + 4*q);
      z0[2*q]   = f2fma(wp.x, xa, z0[2*q]);
      z0[2*q+1] = f2fma(wp.y, xa, z0[2*q+1]);
      z1[2*q]   = f2fma(wp.x, xb, z1[2*q]);
      z1[2*q+1] = f2fma(wp.y, xb, z1[2*q+1]);
    }
  }
  #pragma unroll
  for (int q = 0; q < 4; q++){
    ulonglong2 s = *reinterpret_cast<const ulonglong2*>(S2 + 4*q);
    acc0[2*q]   = f2fma(z0[2*q],   s.x, acc0[2*q]);
    acc0[2*q+1] = f2fma(z0[2*q+1], s.y, acc0[2*q+1]);
    acc1[2*q]   = f2fma(z1[2*q],   s.x, acc1[2*q]);
    acc1[2*q+1] = f2fma(z1[2*q+1], s.y, acc1[2*q+1]);
  }
}

// ---- one full st_gcn layer (7 relation branches) ----
template<int CIN>
__device__ __forceinline__ void run_layer(const float* sP, float* sA,
    const float* WgL, const float* WtL, const float* BgL,
    const float* S1L, const float* B1L, const float* S2L,
    const float (&xr0)[18], const float (&xr1)[18],
    ULL (&acc0)[8], ULL (&acc1)[8],
    bool act, bool has2, int g, int tt, int vw, int v0, int v1, int nd0, int nd1)
{
  // spatial branches k = 0..3 (graph axis V)
  #pragma unroll 1
  for (int k = 0; k < 4; k++){
    if (act) conv_a<CIN>(WgL + k*CIN*16, BgL + k*16, xr0, xr1, sA, nd0, nd1, has2);
    __syncthreads();
    if (act){
      ULL ag0[8], ag1[8];
      #pragma unroll
      for (int op = 0; op < 8; op++){ ag0[op] = 0ULL; ag1[op] = 0ULL; }
      const float* A = sP + P_ASP + k*289;
      #pragma unroll 1
      for (int i = 0; i < 17; i++){
        ULL a0 = pkdup(A[v0*17 + i]);
        ULL a1 = pkdup(A[v1*17 + i]);
        const ulonglong2* yr = reinterpret_cast<const ulonglong2*>(sA + (g*17 + i)*ST);
        #pragma unroll
        for (int q = 0; q < 4; q++){
          ulonglong2 yv = yr[q];
          ag0[2*q]   = f2fma(yv.x, a0, ag0[2*q]);
          ag0[2*q+1] = f2fma(yv.y, a0, ag0[2*q+1]);
          ag1[2*q]   = f2fma(yv.x, a1, ag1[2*q]);
          ag1[2*q+1] = f2fma(yv.y, a1, ag1[2*q+1]);
        }
      }
      post_agg(WtL + k*256, S1L + k*16, B1L + k*16, S2L + k*16, ag0, ag1, acc0, acc1);
    }
    __syncthreads();
  }
  // temporal branches k = 4..5 (graph axis T)
  #pragma unroll 1
  for (int k = 4; k < 6; k++){
    if (act) conv_a<CIN>(WgL + k*CIN*16, BgL + k*16, xr0, xr1, sA, nd0, nd1, has2);
    __syncthreads();
    if (act){
      ULL ag0[8], ag1[8];
      #pragma unroll
      for (int op = 0; op < 8; op++){ ag0[op] = 0ULL; ag1[op] = 0ULL; }
      const float* A = sP + P_ATM + (k - 4)*25 + tt*5;
      #pragma unroll
      for (int tp = 0; tp < 5; tp++){
        ULL ap = pkdup(A[tp]);
        const ulonglong2* y0r = reinterpret_cast<const ulonglong2*>(sA + ((vw*5 + tp)*17 + v0)*ST);
        const ulonglong2* y1r = reinterpret_cast<const ulonglong2*>(sA + ((vw*5 + tp)*17 + v1)*ST);
        #pragma unroll
        for (int q = 0; q < 4; q++){
          ulonglong2 yv = y0r[q];
          ag0[2*q]   = f2fma(yv.x, ap, ag0[2*q]);
          ag0[2*q+1] = f2fma(yv.y, ap, ag0[2*q+1]);
          ulonglong2 yw = y1r[q];
          ag1[2*q]   = f2fma(yw.x, ap, ag1[2*q]);
          ag1[2*q+1] = f2fma(yw.y, ap, ag1[2*q+1]);
        }
      }
      post_agg(WtL + k*256, S1L + k*16, B1L + k*16, S2L + k*16, ag0, ag1, acc0, acc1);
    }
    __syncthreads();
  }
  // views branch k = 6 (graph axis Views)
  {
    const int k = 6;
    if (act) conv_a<CIN>(WgL + k*CIN*16, BgL + k*16, xr0, xr1, sA, nd0, nd1, has2);
    __syncthreads();
    if (act){
      ULL ag0[8], ag1[8];
      #pragma unroll
      for (int op = 0; op < 8; op++){ ag0[op] = 0ULL; ag1[op] = 0ULL; }
      const float* A = sP + P_AVW + vw*4;
      #pragma unroll
      for (int wq = 0; wq < 4; wq++){
        ULL ap = pkdup(A[wq]);
        const ulonglong2* y0r = reinterpret_cast<const ulonglong2*>(sA + ((wq*5 + tt)*17 + v0)*ST);
        const ulonglong2* y1r = reinterpret_cast<const ulonglong2*>(sA + ((wq*5 + tt)*17 + v1)*ST);
        #pragma unroll
        for (int q = 0; q < 4; q++){
          ulonglong2 yv = y0r[q];
          ag0[2*q]   = f2fma(yv.x, ap, ag0[2*q]);
          ag0[2*q+1] = f2fma(yv.y, ap, ag0[2*q+1]);
          ulonglong2 yw = y1r[q];
          ag1[2*q]   = f2fma(yw.x, ap, ag1[2*q]);
          ag1[2*q+1] = f2fma(yw.y, ap, ag1[2*q+1]);
        }
      }
      post_agg(WtL + k*256, S1L + k*16, B1L + k*16, S2L + k*16, ag0, ag1, acc0, acc1);
    }
    __syncthreads();
  }
}

// ---------------- fused 3-layer ST-GCN: one CTA per (n, hw) ----------------
__global__ __launch_bounds__(192, 2)
void stgcn_kernel(const float* __restrict__ x, float* __restrict__ out)
{
  extern __shared__ float smf[];
  float* sP = smf;
  float* sA = smf + S_ACT;   // 340 rows x stride 20: input x (L0), then y exchange buffer

  const int hw  = blockIdx.x;
  const int n   = blockIdx.y;
  const int tid = threadIdx.x;

  for (int i = tid; i < P_TOT; i += 192) sP[i] = gP[i];
  {
    const float* xb = x + ((size_t)n * NODES * 18) * HW + hw;
    for (int i = tid; i < NODES * 18; i += 192){
      int node = i / 18, c = i % 18;
      sA[node*ST + c] = xb[(size_t)i * HW];
    }
  }
  __syncthreads();

  const bool act  = tid < 180;
  const int  g    = tid / 9;     // g = vw*5 + tt   (0..19)
  const int  j    = tid % 9;     // v-pair slot
  const int  vw   = g / 5, tt = g % 5;
  const bool has2 = (j < 8);
  const int  v0   = 2*j;                 // j==8 -> v0 = 16
  const int  v1   = has2 ? (2*j + 1) : v0;
  const int  nd0  = g*17 + v0, nd1 = g*17 + v1;

  ULL acc0[8], acc1[8];
  float xr0[18], xr1[18];

  // ---- layer 0 (CIN=18, no residual) ----
  if (act){
    #pragma unroll
    for (int c = 0; c < 18; c++){ xr0[c] = sA[nd0*ST + c]; xr1[c] = sA[nd1*ST + c]; }
    const float* CI = sP + P_CI;
    #pragma unroll
    for (int op = 0; op < 8; op++){ ULL ci = lds2(CI + 2*op); acc0[op] = ci; acc1[op] = ci; }
  }
  __syncthreads();   // all x reads done before y overwrites sA

  run_layer<18>(sP, sA, sP + P_WG0, sP + P_WT, sP + P_BG, sP + P_S1, sP + P_B1, sP + P_S2,
                xr0, xr1, acc0, acc1, act, has2, g, tt, vw, v0, v1, nd0, nd1);

  // ---- layers 1,2 (CIN=16, residual x7 folded into init) ----
  #pragma unroll 1
  for (int l = 1; l < 3; l++){
    if (act){
      const float* CI = sP + P_CI + l*16;
      #pragma unroll
      for (int op = 0; op < 8; op++){
        float2 a = up2(acc0[op]);
        float2 b = up2(acc1[op]);
        float xa0 = fmaxf(a.x, 0.f), xa1 = fmaxf(a.y, 0.f);
        float xb0 = fmaxf(b.x, 0.f), xb1 = fmaxf(b.y, 0.f);
        xr0[2*op] = xa0; xr0[2*op+1] = xa1;
        xr1[2*op] = xb0; xr1[2*op+1] = xb1;
        acc0[op] = pk(fmaf(7.f, xa0, CI[2*op]), fmaf(7.f, xa1, CI[2*op+1]));
        acc1[op] = pk(fmaf(7.f, xb0, CI[2*op]), fmaf(7.f, xb1, CI[2*op+1]));
      }
    }
    const float* WgL = sP + (l == 1 ? P_WG1 : P_WG2);
    run_layer<16>(sP, sA, WgL, sP + P_WT + l*1792, sP + P_BG + l*112,
                  sP + P_S1 + l*112, sP + P_B1 + l*112, sP + P_S2 + l*112,
                  xr0, xr1, acc0, acc1, act, has2, g, tt, vw, v0, v1, nd0, nd1);
  }

  // ---- final ReLU + output ----
  if (act){
    float* o0 = out + ((size_t)(n*NODES + nd0) * 16) * HW + hw;
    #pragma unroll
    for (int op = 0; op < 8; op++){
      float2 a = up2(acc0[op]);
      o0[(size_t)(2*op)     * HW] = fmaxf(a.x, 0.f);
      o0[(size_t)(2*op + 1) * HW] = fmaxf(a.y, 0.f);
    }
    if (has2){
      float* o1 = out + ((size_t)(n*NODES + nd1) * 16) * HW + hw;
      #pragma unroll
      for (int op = 0; op < 8; op++){
        float2 b = up2(acc1[op]);
        o1[(size_t)(2*op)     * HW] = fmaxf(b.x, 0.f);
        o1[(size_t)(2*op + 1) * HW] = fmaxf(b.y, 0.f);
      }
    }
  }
}

extern "C" void kernel_launch(void* const* d_in, const int* in_sizes, int n_in,
                              void* d_out, int out_size)
{
  (void)in_sizes; (void)n_in; (void)out_size;
  const float* x    = (const float*)d_in[0];
  const float* A_sp = (const float*)d_in[1];
  const float* A_tm = (const float*)d_in[2];
  const float* A_vw = (const float*)d_in[3];
  const float* Wg0  = (const float*)d_in[4];
  const float* bg0  = (const float*)d_in[5];
  const float* Wg   = (const float*)d_in[6];
  const float* bg   = (const float*)d_in[7];
  const float* bn1g = (const float*)d_in[8];
  const float* bn1b = (const float*)d_in[9];
  const float* Wt   = (const float*)d_in[10];
  const float* bt   = (const float*)d_in[11];
  const float* bn2g = (const float*)d_in[12];
  const float* bn2b = (const float*)d_in[13];

  cudaFuncSetAttribute(stgcn_kernel, cudaFuncAttributeMaxDynamicSharedMemorySize, SM_BYTES);

  prep_kernel<<<1, 256>>>(A_sp, A_tm, A_vw, Wg0, bg0, Wg, bg,
                          bn1g, bn1b, Wt, bt, bn2g, bn2b);
  stgcn_kernel<<<dim3(HW, NB), 192, SM_BYTES>>>(x, (float*)d_out);
}